// round 1
// baseline (speedup 1.0000x reference)
#include <cuda_runtime.h>

#define BSZ   4
#define LSEQ  2048
#define DM    1024
#define NH    16
#define HD    64
#define MROWS (BSZ * LSEQ)   // 8192

// Scratch (device globals — no allocation allowed in kernel_launch)
__device__ float g_q[MROWS * DM];
__device__ float g_k[MROWS * DM];
__device__ float g_v[MROWS * DM];
__device__ float g_ctx[MROWS * DM];

// ---------------------------------------------------------------------------
// SGEMM: C[M,N] = A[M,K] @ W[K,N] + bias, M=8192, N=K=1024.
// BM=BN=128, BK=8, 256 threads, 8x8 microtile.
// ---------------------------------------------------------------------------
__global__ __launch_bounds__(256) void gemm_bias_kernel(
    const float* __restrict__ A, const float* __restrict__ W,
    const float* __restrict__ bias, float* __restrict__ C)
{
    const int K = DM, N = DM;
    __shared__ float As[8][128];
    __shared__ float Bs[8][128];

    const int tid = threadIdx.x;
    const int ty = tid >> 4;          // 0..15 (row group)
    const int tx = tid & 15;          // 0..15 (col group)
    const int rowBlock = blockIdx.y * 128;
    const int colBlock = blockIdx.x * 128;

    // A-tile load mapping: 128 rows x 8 k, one float4 per thread
    const int aRow = tid >> 1;            // 0..127
    const int aCol = (tid & 1) * 4;       // 0 or 4
    // W-tile load mapping: 8 k-rows x 128 n, one float4 per thread
    const int bRow = tid >> 5;            // 0..7
    const int bCol = (tid & 31) * 4;      // 0..124

    const float* Aptr = A + (size_t)(rowBlock + aRow) * K + aCol;
    const float* Wptr = W + (size_t)bRow * N + colBlock + bCol;

    float acc[8][8];
#pragma unroll
    for (int i = 0; i < 8; i++)
#pragma unroll
        for (int j = 0; j < 8; j++) acc[i][j] = 0.f;

    for (int k0 = 0; k0 < K; k0 += 8) {
        float4 va = *(const float4*)(Aptr + k0);
        float4 vb = *(const float4*)(Wptr + (size_t)k0 * N);
        As[aCol + 0][aRow] = va.x;
        As[aCol + 1][aRow] = va.y;
        As[aCol + 2][aRow] = va.z;
        As[aCol + 3][aRow] = va.w;
        *(float4*)&Bs[bRow][bCol] = vb;
        __syncthreads();

#pragma unroll
        for (int kk = 0; kk < 8; kk++) {
            float a[8], b[8];
#pragma unroll
            for (int i = 0; i < 8; i++) a[i] = As[kk][ty * 8 + i];
#pragma unroll
            for (int j = 0; j < 8; j++) b[j] = Bs[kk][tx * 8 + j];
#pragma unroll
            for (int i = 0; i < 8; i++)
#pragma unroll
                for (int j = 0; j < 8; j++)
                    acc[i][j] = fmaf(a[i], b[j], acc[i][j]);
        }
        __syncthreads();
    }

    float bv[8];
#pragma unroll
    for (int j = 0; j < 8; j++) bv[j] = bias[colBlock + tx * 8 + j];

#pragma unroll
    for (int i = 0; i < 8; i++) {
        float* cp = C + (size_t)(rowBlock + ty * 8 + i) * N + colBlock + tx * 8;
        float4 o0 = make_float4(acc[i][0] + bv[0], acc[i][1] + bv[1],
                                acc[i][2] + bv[2], acc[i][3] + bv[3]);
        float4 o1 = make_float4(acc[i][4] + bv[4], acc[i][5] + bv[5],
                                acc[i][6] + bv[6], acc[i][7] + bv[7]);
        *(float4*)cp = o0;
        *(float4*)(cp + 4) = o1;
    }
}

// ---------------------------------------------------------------------------
// Flash-style attention. Grid: (L/64, B*H). 256 threads.
// q,k,v,ctx layout: [B*L, D] with head h at column h*64.
// ---------------------------------------------------------------------------
__global__ __launch_bounds__(256) void attn_kernel(
    const float* __restrict__ qg, const float* __restrict__ kg,
    const float* __restrict__ vg, float* __restrict__ ctx)
{
    extern __shared__ float sm[];
    float* qs   = sm;                 // 64*65
    float* ks   = qs + 64 * 65;       // 64*65
    float* vs   = ks + 64 * 65;       // 64*65
    float* ps   = vs + 64 * 65;       // 64*65
    float* m_sh = ps + 64 * 65;       // 64
    float* l_sh = m_sh + 64;          // 64
    float* a_sh = l_sh + 64;          // 64

    const int tid = threadIdx.x;
    const int ty = tid >> 4;          // 0..15
    const int tx = tid & 15;          // 0..15
    const int bh = blockIdx.y;
    const int b = bh >> 4;
    const int h = bh & 15;
    const int q0 = blockIdx.x * 64;
    const float scale = 0.125f;       // 1/sqrt(64)

    // Load q tile (64 rows x 64 e), fold in scale
    const float* qbase = qg + ((size_t)(b * LSEQ + q0)) * DM + h * HD;
    for (int p = tid; p < 64 * 16; p += 256) {
        int r = p >> 4;
        int c4 = (p & 15) << 2;
        float4 v4 = *(const float4*)(qbase + (size_t)r * DM + c4);
        qs[r * 65 + c4 + 0] = v4.x * scale;
        qs[r * 65 + c4 + 1] = v4.y * scale;
        qs[r * 65 + c4 + 2] = v4.z * scale;
        qs[r * 65 + c4 + 3] = v4.w * scale;
    }
    if (tid < 64) { m_sh[tid] = -1e30f; l_sh[tid] = 0.f; }

    float acc[4][4];
#pragma unroll
    for (int i = 0; i < 4; i++)
#pragma unroll
        for (int j = 0; j < 4; j++) acc[i][j] = 0.f;

    const float* kbase = kg + ((size_t)(b * LSEQ)) * DM + h * HD;
    const float* vbase = vg + ((size_t)(b * LSEQ)) * DM + h * HD;

    __syncthreads();

    for (int s0 = 0; s0 < LSEQ; s0 += 64) {
        // Load K and V chunks (64 x 64 each)
        for (int p = tid; p < 64 * 16; p += 256) {
            int r = p >> 4;
            int c4 = (p & 15) << 2;
            float4 kk4 = *(const float4*)(kbase + (size_t)(s0 + r) * DM + c4);
            float4 vv4 = *(const float4*)(vbase + (size_t)(s0 + r) * DM + c4);
            ks[r * 65 + c4 + 0] = kk4.x;
            ks[r * 65 + c4 + 1] = kk4.y;
            ks[r * 65 + c4 + 2] = kk4.z;
            ks[r * 65 + c4 + 3] = kk4.w;
            vs[r * 65 + c4 + 0] = vv4.x;
            vs[r * 65 + c4 + 1] = vv4.y;
            vs[r * 65 + c4 + 2] = vv4.z;
            vs[r * 65 + c4 + 3] = vv4.w;
        }
        __syncthreads();

        // Scores: sc[i][j] = sum_e q[ty*4+i][e] * k[tx*4+j][e]
        float sc[4][4];
#pragma unroll
        for (int i = 0; i < 4; i++)
#pragma unroll
            for (int j = 0; j < 4; j++) sc[i][j] = 0.f;

        for (int e = 0; e < 64; e++) {
            float qv[4], kv[4];
#pragma unroll
            for (int i = 0; i < 4; i++) qv[i] = qs[(ty * 4 + i) * 65 + e];
#pragma unroll
            for (int j = 0; j < 4; j++) kv[j] = ks[(tx * 4 + j) * 65 + e];
#pragma unroll
            for (int i = 0; i < 4; i++)
#pragma unroll
                for (int j = 0; j < 4; j++)
                    sc[i][j] = fmaf(qv[i], kv[j], sc[i][j]);
        }
#pragma unroll
        for (int i = 0; i < 4; i++)
#pragma unroll
            for (int j = 0; j < 4; j++)
                ps[(ty * 4 + i) * 65 + tx * 4 + j] = sc[i][j];
        __syncthreads();

        // Online softmax: 4 threads per row, 16 cols each
        {
            int row = tid >> 2;
            int seg = tid & 3;
            float* prow = ps + row * 65 + seg * 16;
            float lm = -1e30f;
#pragma unroll
            for (int c = 0; c < 16; c++) lm = fmaxf(lm, prow[c]);
            lm = fmaxf(lm, __shfl_xor_sync(0xffffffffu, lm, 1));
            lm = fmaxf(lm, __shfl_xor_sync(0xffffffffu, lm, 2));
            float m_old = m_sh[row];
            float m_new = fmaxf(m_old, lm);
            float lsum = 0.f;
#pragma unroll
            for (int c = 0; c < 16; c++) {
                float pv = __expf(prow[c] - m_new);
                prow[c] = pv;
                lsum += pv;
            }
            lsum += __shfl_xor_sync(0xffffffffu, lsum, 1);
            lsum += __shfl_xor_sync(0xffffffffu, lsum, 2);
            if (seg == 0) {
                float alpha = __expf(m_old - m_new);
                a_sh[row] = alpha;
                m_sh[row] = m_new;
                l_sh[row] = l_sh[row] * alpha + lsum;
            }
        }
        __syncthreads();

        // O update: rescale by alpha, accumulate P @ V
        float al[4];
#pragma unroll
        for (int i = 0; i < 4; i++) al[i] = a_sh[ty * 4 + i];
#pragma unroll
        for (int i = 0; i < 4; i++)
#pragma unroll
            for (int j = 0; j < 4; j++) acc[i][j] *= al[i];

        for (int s = 0; s < 64; s++) {
            float pv[4], vv[4];
#pragma unroll
            for (int i = 0; i < 4; i++) pv[i] = ps[(ty * 4 + i) * 65 + s];
#pragma unroll
            for (int j = 0; j < 4; j++) vv[j] = vs[s * 65 + tx * 4 + j];
#pragma unroll
            for (int i = 0; i < 4; i++)
#pragma unroll
                for (int j = 0; j < 4; j++)
                    acc[i][j] = fmaf(pv[i], vv[j], acc[i][j]);
        }
        __syncthreads();
    }

    // Final normalize + write ctx
    float inv[4];
#pragma unroll
    for (int i = 0; i < 4; i++) inv[i] = 1.f / l_sh[ty * 4 + i];
    float* cb = ctx + ((size_t)(b * LSEQ + q0 + ty * 4)) * DM + h * HD + tx * 4;
#pragma unroll
    for (int i = 0; i < 4; i++)
#pragma unroll
        for (int j = 0; j < 4; j++)
            cb[(size_t)i * DM + j] = acc[i][j] * inv[i];
}

// ---------------------------------------------------------------------------
extern "C" void kernel_launch(void* const* d_in, const int* in_sizes, int n_in,
                              void* d_out, int out_size)
{
    const float* queries = (const float*)d_in[0];
    const float* keys    = (const float*)d_in[1];
    const float* values  = (const float*)d_in[2];
    const float* Wq      = (const float*)d_in[3];
    const float* bq      = (const float*)d_in[4];
    const float* Wk      = (const float*)d_in[5];
    const float* bk      = (const float*)d_in[6];
    const float* Wv      = (const float*)d_in[7];
    const float* bv      = (const float*)d_in[8];
    const float* Wo      = (const float*)d_in[9];
    const float* bo      = (const float*)d_in[10];
    float* out = (float*)d_out;

    float *qb, *kb, *vb, *cb;
    cudaGetSymbolAddress((void**)&qb, g_q);
    cudaGetSymbolAddress((void**)&kb, g_k);
    cudaGetSymbolAddress((void**)&vb, g_v);
    cudaGetSymbolAddress((void**)&cb, g_ctx);

    dim3 ggrid(DM / 128, MROWS / 128);
    gemm_bias_kernel<<<ggrid, 256>>>(queries, Wq, bq, qb);
    gemm_bias_kernel<<<ggrid, 256>>>(keys,    Wk, bk, kb);
    gemm_bias_kernel<<<ggrid, 256>>>(values,  Wv, bv, vb);

    size_t shmem = (4 * 64 * 65 + 3 * 64) * sizeof(float);  // 67328 B
    cudaFuncSetAttribute(attn_kernel,
                         cudaFuncAttributeMaxDynamicSharedMemorySize,
                         (int)shmem);
    attn_kernel<<<dim3(LSEQ / 64, BSZ * NH), 256, shmem>>>(qb, kb, vb, cb);

    gemm_bias_kernel<<<ggrid, 256>>>(cb, Wo, bo, out);
}

// round 2
// speedup vs baseline: 1.1294x; 1.1294x over previous
#include <cuda_runtime.h>

#define BSZ   4
#define LSEQ  2048
#define DM    1024
#define NH    16
#define HD    64
#define MROWS (BSZ * LSEQ)   // 8192

// Scratch (device globals — no allocation allowed)
__device__ float g_q[MROWS * DM];
__device__ float g_k[MROWS * DM];
__device__ float g_v[MROWS * DM];
__device__ float g_ctx[MROWS * DM];

__device__ __forceinline__ unsigned tf32_rna(float x) {
    unsigned u;
    asm("cvt.rna.tf32.f32 %0, %1;" : "=r"(u) : "f"(x));
    return u;
}

__device__ __forceinline__ void mma8(float* c, const unsigned* a, const unsigned* b) {
    asm volatile(
        "mma.sync.aligned.m16n8k8.row.col.f32.tf32.tf32.f32 "
        "{%0,%1,%2,%3}, {%4,%5,%6,%7}, {%8,%9}, {%0,%1,%2,%3};\n"
        : "+f"(c[0]), "+f"(c[1]), "+f"(c[2]), "+f"(c[3])
        : "r"(a[0]), "r"(a[1]), "r"(a[2]), "r"(a[3]),
          "r"(b[0]), "r"(b[1]));
}

// ---------------------------------------------------------------------------
// tf32x3 split-precision GEMM: C[M,N] = A[M,K] @ W[K,N] + bias
// BM=BN=128, BK=32, 256 threads (8 warps, 2x4), warp tile 64x32.
// A and W split into (hi, lo) tf32 pairs stored as float2 in shared.
// ---------------------------------------------------------------------------
#define GSTRIDE 130   // float2 row stride (128 + 2 pad)

__global__ __launch_bounds__(256) void gemm_tf32x3_kernel(
    const float* __restrict__ A, const float* __restrict__ W,
    const float* __restrict__ bias, float* __restrict__ C)
{
    extern __shared__ float2 sm2[];
    float2* As = sm2;                  // [32][GSTRIDE] (k, m)
    float2* Bs = sm2 + 32 * GSTRIDE;   // [32][GSTRIDE] (k, n)

    const int tid  = threadIdx.x;
    const int lane = tid & 31;
    const int warp = tid >> 5;
    const int g  = lane >> 2;
    const int tg = lane & 3;
    const int m0w = (warp & 1) * 64;
    const int n0w = (warp >> 1) * 32;
    const int rowBlock = blockIdx.y * 128;
    const int colBlock = blockIdx.x * 128;

    const int arow = tid >> 1;          // 0..127
    const int acb  = (tid & 1) * 16;    // 0 or 16
    const int brow = tid >> 3;          // 0..31
    const int bcb  = (tid & 7) * 16;    // 0..112

    const float* Ap = A + (size_t)(rowBlock + arow) * DM + acb;
    const float* Wp = W + (size_t)brow * DM + colBlock + bcb;

    float4 pa[4], pb[4];
#pragma unroll
    for (int i = 0; i < 4; i++) {
        pa[i] = *(const float4*)(Ap + 4 * i);
        pb[i] = *(const float4*)(Wp + 4 * i);
    }

    float c[4][4][4];
#pragma unroll
    for (int mf = 0; mf < 4; mf++)
#pragma unroll
        for (int nf = 0; nf < 4; nf++)
#pragma unroll
            for (int i = 0; i < 4; i++) c[mf][nf][i] = 0.f;

    for (int kt = 0; kt < 32; kt++) {
        // stage tiles to shared (split hi/lo)
#pragma unroll
        for (int i = 0; i < 4; i++) {
            const float* pav = (const float*)&pa[i];
            const float* pbv = (const float*)&pb[i];
#pragma unroll
            for (int j = 0; j < 4; j++) {
                float x  = pav[j];
                float xh = __uint_as_float(tf32_rna(x));
                As[(acb + 4 * i + j) * GSTRIDE + arow] = make_float2(xh, x - xh);
                float y  = pbv[j];
                float yh = __uint_as_float(tf32_rna(y));
                Bs[brow * GSTRIDE + bcb + 4 * i + j] = make_float2(yh, y - yh);
            }
        }
        __syncthreads();

        if (kt < 31) {
            const float* Ap2 = Ap + (kt + 1) * 32;
            const float* Wp2 = Wp + (size_t)(kt + 1) * 32 * DM;
#pragma unroll
            for (int i = 0; i < 4; i++) {
                pa[i] = *(const float4*)(Ap2 + 4 * i);
                pb[i] = *(const float4*)(Wp2 + 4 * i);
            }
        }

#pragma unroll
        for (int ks = 0; ks < 4; ks++) {
            const int k8 = ks * 8;
            unsigned ah[4][4], al[4][4], bh[4][2], bl[4][2];
#pragma unroll
            for (int mf = 0; mf < 4; mf++) {
                int mi = m0w + mf * 16 + g;
                float2 v0 = As[(k8 + tg) * GSTRIDE + mi];
                float2 v1 = As[(k8 + tg) * GSTRIDE + mi + 8];
                float2 v2 = As[(k8 + tg + 4) * GSTRIDE + mi];
                float2 v3 = As[(k8 + tg + 4) * GSTRIDE + mi + 8];
                ah[mf][0] = __float_as_uint(v0.x); al[mf][0] = __float_as_uint(v0.y);
                ah[mf][1] = __float_as_uint(v1.x); al[mf][1] = __float_as_uint(v1.y);
                ah[mf][2] = __float_as_uint(v2.x); al[mf][2] = __float_as_uint(v2.y);
                ah[mf][3] = __float_as_uint(v3.x); al[mf][3] = __float_as_uint(v3.y);
            }
#pragma unroll
            for (int nf = 0; nf < 4; nf++) {
                int ni = n0w + nf * 8 + g;
                float2 w0 = Bs[(k8 + tg) * GSTRIDE + ni];
                float2 w1 = Bs[(k8 + tg + 4) * GSTRIDE + ni];
                bh[nf][0] = __float_as_uint(w0.x); bl[nf][0] = __float_as_uint(w0.y);
                bh[nf][1] = __float_as_uint(w1.x); bl[nf][1] = __float_as_uint(w1.y);
            }
#pragma unroll
            for (int mf = 0; mf < 4; mf++)
#pragma unroll
                for (int nf = 0; nf < 4; nf++) {
                    mma8(c[mf][nf], ah[mf], bh[nf]);
                    mma8(c[mf][nf], al[mf], bh[nf]);
                    mma8(c[mf][nf], ah[mf], bl[nf]);
                }
        }
        __syncthreads();
    }

#pragma unroll
    for (int mf = 0; mf < 4; mf++) {
#pragma unroll
        for (int nf = 0; nf < 4; nf++) {
            int col = colBlock + n0w + nf * 8 + 2 * tg;
            float2 bv = *(const float2*)(bias + col);
            int r0 = rowBlock + m0w + mf * 16 + g;
            *(float2*)(C + (size_t)r0 * DM + col) =
                make_float2(c[mf][nf][0] + bv.x, c[mf][nf][1] + bv.y);
            *(float2*)(C + (size_t)(r0 + 8) * DM + col) =
                make_float2(c[mf][nf][2] + bv.x, c[mf][nf][3] + bv.y);
        }
    }
}

// ---------------------------------------------------------------------------
// Flash attention with tf32 mma. Block = 128 threads (4 warps).
// Warp w owns query rows [w*16, w*16+16). q-tile 64, S-chunk 64.
// After the K/V tile barrier everything is warp-local.
// ---------------------------------------------------------------------------
#define AP 68   // padded float row stride

__global__ __launch_bounds__(128) void attn_mma_kernel(
    const float* __restrict__ qg, const float* __restrict__ kg,
    const float* __restrict__ vg, float* __restrict__ ctx)
{
    extern __shared__ float smf[];
    float* qs   = smf;               // [64][AP]
    float* ks   = qs + 64 * AP;
    float* vs   = ks + 64 * AP;
    float* ps   = vs + 64 * AP;
    float* m_sh = ps + 64 * AP;      // 64
    float* l_sh = m_sh + 64;         // 64
    float* a_sh = l_sh + 64;         // 64

    const int tid  = threadIdx.x;
    const int lane = tid & 31;
    const int warp = tid >> 5;
    const int g  = lane >> 2;
    const int tg = lane & 3;
    const int w16 = warp * 16;
    const int b = blockIdx.y >> 4;
    const int h = blockIdx.y & 15;
    const int q0 = blockIdx.x * 64;
    const float scale = 0.125f;      // 1/sqrt(64)

    const int lr = tid >> 1;             // 0..63 (warp-local rows for q)
    const int lc = (tid & 1) * 32;

    // Load Q (scaled, tf32-rounded). Rows 16w..16w+15 loaded by warp w itself.
    const float* qbase = qg + (size_t)(b * LSEQ + q0) * DM + h * HD;
#pragma unroll
    for (int i = 0; i < 8; i++) {
        float4 v4 = *(const float4*)(qbase + (size_t)lr * DM + lc + 4 * i);
        float4 t;
        t.x = __uint_as_float(tf32_rna(v4.x * scale));
        t.y = __uint_as_float(tf32_rna(v4.y * scale));
        t.z = __uint_as_float(tf32_rna(v4.z * scale));
        t.w = __uint_as_float(tf32_rna(v4.w * scale));
        *(float4*)(qs + lr * AP + lc + 4 * i) = t;
    }
    if (lane < 16) { m_sh[w16 + lane] = -1e30f; l_sh[w16 + lane] = 0.f; }

    float o[8][4];
#pragma unroll
    for (int nf = 0; nf < 8; nf++)
#pragma unroll
        for (int i = 0; i < 4; i++) o[nf][i] = 0.f;

    const float* kbase = kg + (size_t)(b * LSEQ) * DM + h * HD;
    const float* vbase = vg + (size_t)(b * LSEQ) * DM + h * HD;

    for (int s0 = 0; s0 < LSEQ; s0 += 64) {
        __syncthreads();   // previous chunk's PV done reading ks/vs
#pragma unroll
        for (int i = 0; i < 8; i++) {
            float4 k4 = *(const float4*)(kbase + (size_t)(s0 + lr) * DM + lc + 4 * i);
            float4 v4 = *(const float4*)(vbase + (size_t)(s0 + lr) * DM + lc + 4 * i);
            float4 tk, tv;
            tk.x = __uint_as_float(tf32_rna(k4.x)); tv.x = __uint_as_float(tf32_rna(v4.x));
            tk.y = __uint_as_float(tf32_rna(k4.y)); tv.y = __uint_as_float(tf32_rna(v4.y));
            tk.z = __uint_as_float(tf32_rna(k4.z)); tv.z = __uint_as_float(tf32_rna(v4.z));
            tk.w = __uint_as_float(tf32_rna(k4.w)); tv.w = __uint_as_float(tf32_rna(v4.w));
            *(float4*)(ks + lr * AP + lc + 4 * i) = tk;
            *(float4*)(vs + lr * AP + lc + 4 * i) = tv;
        }
        __syncthreads();   // ks/vs (and first-iter qs/m/l) visible

        // --- scores: S = Q · K^T  (warp rows w16..w16+15, all 64 cols) ---
        float sc[8][4];
#pragma unroll
        for (int nf = 0; nf < 8; nf++)
#pragma unroll
            for (int i = 0; i < 4; i++) sc[nf][i] = 0.f;

#pragma unroll
        for (int k8 = 0; k8 < 64; k8 += 8) {
            unsigned a[4];
            const float* qr0 = qs + (w16 + g) * AP + k8 + tg;
            const float* qr1 = qs + (w16 + g + 8) * AP + k8 + tg;
            a[0] = __float_as_uint(qr0[0]);
            a[1] = __float_as_uint(qr1[0]);
            a[2] = __float_as_uint(qr0[4]);
            a[3] = __float_as_uint(qr1[4]);
#pragma unroll
            for (int nf = 0; nf < 8; nf++) {
                unsigned bb[2];
                const float* kr = ks + (nf * 8 + g) * AP + k8 + tg;
                bb[0] = __float_as_uint(kr[0]);
                bb[1] = __float_as_uint(kr[4]);
                mma8(sc[nf], a, bb);
            }
        }
#pragma unroll
        for (int nf = 0; nf < 8; nf++) {
            *(float2*)(ps + (w16 + g) * AP + nf * 8 + 2 * tg) =
                make_float2(sc[nf][0], sc[nf][1]);
            *(float2*)(ps + (w16 + g + 8) * AP + nf * 8 + 2 * tg) =
                make_float2(sc[nf][2], sc[nf][3]);
        }
        __syncwarp();

        // --- online softmax (2 threads per row; rows are warp-local) ---
        {
            const int row = lr;
            float* prow = ps + row * AP + lc;
            float lm = -1e30f;
#pragma unroll
            for (int cc = 0; cc < 32; cc++) lm = fmaxf(lm, prow[cc]);
            lm = fmaxf(lm, __shfl_xor_sync(0xffffffffu, lm, 1));
            float m_old = m_sh[row];
            float m_new = fmaxf(m_old, lm);
            float lsum = 0.f;
#pragma unroll
            for (int cc = 0; cc < 32; cc++) {
                float pv = __expf(prow[cc] - m_new);
                pv = __uint_as_float(tf32_rna(pv));
                prow[cc] = pv;
                lsum += pv;
            }
            lsum += __shfl_xor_sync(0xffffffffu, lsum, 1);
            if ((tid & 1) == 0) {
                float alpha = __expf(m_old - m_new);
                a_sh[row] = alpha;
                m_sh[row] = m_new;
                l_sh[row] = l_sh[row] * alpha + lsum;
            }
        }
        __syncwarp();

        // --- O update: rescale + P·V ---
        float al0 = a_sh[w16 + g];
        float al1 = a_sh[w16 + g + 8];
#pragma unroll
        for (int nf = 0; nf < 8; nf++) {
            o[nf][0] *= al0; o[nf][1] *= al0;
            o[nf][2] *= al1; o[nf][3] *= al1;
        }
#pragma unroll
        for (int k8 = 0; k8 < 64; k8 += 8) {
            unsigned a[4];
            const float* pr0 = ps + (w16 + g) * AP + k8 + tg;
            const float* pr1 = ps + (w16 + g + 8) * AP + k8 + tg;
            a[0] = __float_as_uint(pr0[0]);
            a[1] = __float_as_uint(pr1[0]);
            a[2] = __float_as_uint(pr0[4]);
            a[3] = __float_as_uint(pr1[4]);
#pragma unroll
            for (int nf = 0; nf < 8; nf++) {
                unsigned bb[2];
                const float* vr = vs + (k8 + tg) * AP + nf * 8 + g;
                bb[0] = __float_as_uint(vr[0]);
                bb[1] = __float_as_uint(vr[4 * AP]);
                mma8(o[nf], a, bb);
            }
        }
    }

    // final normalize + write ctx
    float inv0 = 1.f / l_sh[w16 + g];
    float inv1 = 1.f / l_sh[w16 + g + 8];
    float* cb0 = ctx + (size_t)(b * LSEQ + q0 + w16 + g) * DM + h * HD;
    float* cb1 = ctx + (size_t)(b * LSEQ + q0 + w16 + g + 8) * DM + h * HD;
#pragma unroll
    for (int nf = 0; nf < 8; nf++) {
        *(float2*)(cb0 + nf * 8 + 2 * tg) =
            make_float2(o[nf][0] * inv0, o[nf][1] * inv0);
        *(float2*)(cb1 + nf * 8 + 2 * tg) =
            make_float2(o[nf][2] * inv1, o[nf][3] * inv1);
    }
}

// ---------------------------------------------------------------------------
extern "C" void kernel_launch(void* const* d_in, const int* in_sizes, int n_in,
                              void* d_out, int out_size)
{
    const float* queries = (const float*)d_in[0];
    const float* keys    = (const float*)d_in[1];
    const float* values  = (const float*)d_in[2];
    const float* Wq      = (const float*)d_in[3];
    const float* bq      = (const float*)d_in[4];
    const float* Wk      = (const float*)d_in[5];
    const float* bk      = (const float*)d_in[6];
    const float* Wv      = (const float*)d_in[7];
    const float* bv      = (const float*)d_in[8];
    const float* Wo      = (const float*)d_in[9];
    const float* bo      = (const float*)d_in[10];
    float* out = (float*)d_out;

    float *qb, *kb, *vb, *cb;
    cudaGetSymbolAddress((void**)&qb, g_q);
    cudaGetSymbolAddress((void**)&kb, g_k);
    cudaGetSymbolAddress((void**)&vb, g_v);
    cudaGetSymbolAddress((void**)&cb, g_ctx);

    const size_t gemm_sm = 2 * 32 * GSTRIDE * sizeof(float2);        // 66560
    const size_t attn_sm = (4 * 64 * AP + 3 * 64) * sizeof(float);   // 70400

    cudaFuncSetAttribute(gemm_tf32x3_kernel,
                         cudaFuncAttributeMaxDynamicSharedMemorySize, (int)gemm_sm);
    cudaFuncSetAttribute(attn_mma_kernel,
                         cudaFuncAttributeMaxDynamicSharedMemorySize, (int)attn_sm);

    dim3 ggrid(DM / 128, MROWS / 128);
    gemm_tf32x3_kernel<<<ggrid, 256, gemm_sm>>>(queries, Wq, bq, qb);
    gemm_tf32x3_kernel<<<ggrid, 256, gemm_sm>>>(keys,    Wk, bk, kb);
    gemm_tf32x3_kernel<<<ggrid, 256, gemm_sm>>>(values,  Wv, bv, vb);

    attn_mma_kernel<<<dim3(LSEQ / 64, BSZ * NH), 128, attn_sm>>>(qb, kb, vb, cb);

    gemm_tf32x3_kernel<<<ggrid, 256, gemm_sm>>>(cb, Wo, bo, out);
}

// round 3
// speedup vs baseline: 1.4529x; 1.2865x over previous
#include <cuda_runtime.h>

#define BSZ   4
#define LSEQ  2048
#define DM    1024
#define NH    16
#define HD    64
#define MROWS (BSZ * LSEQ)   // 8192

// Scratch (device globals — no allocation allowed)
__device__ float g_q[MROWS * DM];
__device__ float g_k[MROWS * DM];
__device__ float g_v[MROWS * DM];
__device__ float g_ctx[MROWS * DM];

__device__ __forceinline__ unsigned tf32_rna(float x) {
    unsigned u;
    asm("cvt.rna.tf32.f32 %0, %1;" : "=r"(u) : "f"(x));
    return u;
}
__device__ __forceinline__ float tf32f(float x) {
    return __uint_as_float(tf32_rna(x));
}

__device__ __forceinline__ void mma8(float* c, const unsigned* a, const unsigned* b) {
    asm volatile(
        "mma.sync.aligned.m16n8k8.row.col.f32.tf32.tf32.f32 "
        "{%0,%1,%2,%3}, {%4,%5,%6,%7}, {%8,%9}, {%0,%1,%2,%3};\n"
        : "+f"(c[0]), "+f"(c[1]), "+f"(c[2]), "+f"(c[3])
        : "r"(a[0]), "r"(a[1]), "r"(a[2]), "r"(a[3]),
          "r"(b[0]), "r"(b[1]));
}

// ---------------------------------------------------------------------------
// tf32x2 GEMM (A split hi/lo, B single-rounded): C = A @ W + bias
// BM=BN=128, BK=32, 256 threads (8 warps, 2x4), warp tile 64x32.
// ---------------------------------------------------------------------------
#define ASTRIDE 130   // float2 words per k-row of As (128 + 2 pad)
#define BSTRIDE 136   // floats per k-row of Bs (128 + 8 pad, conflict-free)

__global__ __launch_bounds__(256) void gemm_tf32x2_kernel(
    const float* __restrict__ A, const float* __restrict__ W,
    const float* __restrict__ bias, float* __restrict__ C)
{
    extern __shared__ char smc[];
    float2* As = (float2*)smc;                                   // [32][ASTRIDE]
    float*  Bs = (float*)(smc + 32 * ASTRIDE * sizeof(float2));  // [32][BSTRIDE]

    const int tid  = threadIdx.x;
    const int lane = tid & 31;
    const int warp = tid >> 5;
    const int g  = lane >> 2;
    const int tg = lane & 3;
    const int m0w = (warp & 1) * 64;
    const int n0w = (warp >> 1) * 32;
    const int rowBlock = blockIdx.y * 128;
    const int colBlock = blockIdx.x * 128;

    const int arow = tid >> 1;          // 0..127
    const int acb  = (tid & 1) * 16;    // 0 or 16
    const int brow = tid >> 3;          // 0..31
    const int bcb  = (tid & 7) * 16;    // 0..112

    const float* Ap = A + (size_t)(rowBlock + arow) * DM + acb;
    const float* Wp = W + (size_t)brow * DM + colBlock + bcb;

    float4 pa[4], pb[4];
#pragma unroll
    for (int i = 0; i < 4; i++) {
        pa[i] = *(const float4*)(Ap + 4 * i);
        pb[i] = *(const float4*)(Wp + 4 * i);
    }

    float c[4][4][4];
#pragma unroll
    for (int mf = 0; mf < 4; mf++)
#pragma unroll
        for (int nf = 0; nf < 4; nf++)
#pragma unroll
            for (int i = 0; i < 4; i++) c[mf][nf][i] = 0.f;

    for (int kt = 0; kt < 32; kt++) {
#pragma unroll
        for (int i = 0; i < 4; i++) {
            const float* pav = (const float*)&pa[i];
#pragma unroll
            for (int j = 0; j < 4; j++) {
                float x  = pav[j];
                float xh = tf32f(x);
                As[(acb + 4 * i + j) * ASTRIDE + arow] = make_float2(xh, x - xh);
            }
            float4 t;
            t.x = tf32f(pb[i].x);
            t.y = tf32f(pb[i].y);
            t.z = tf32f(pb[i].z);
            t.w = tf32f(pb[i].w);
            *(float4*)&Bs[brow * BSTRIDE + bcb + 4 * i] = t;
        }
        __syncthreads();

        if (kt < 31) {
            const float* Ap2 = Ap + (kt + 1) * 32;
            const float* Wp2 = Wp + (size_t)(kt + 1) * 32 * DM;
#pragma unroll
            for (int i = 0; i < 4; i++) {
                pa[i] = *(const float4*)(Ap2 + 4 * i);
                pb[i] = *(const float4*)(Wp2 + 4 * i);
            }
        }

#pragma unroll
        for (int ks = 0; ks < 4; ks++) {
            const int k8 = ks * 8;
            unsigned ah[4][4], al[4][4], bh[4][2];
#pragma unroll
            for (int mf = 0; mf < 4; mf++) {
                int mi = m0w + mf * 16 + g;
                float2 v0 = As[(k8 + tg) * ASTRIDE + mi];
                float2 v1 = As[(k8 + tg) * ASTRIDE + mi + 8];
                float2 v2 = As[(k8 + tg + 4) * ASTRIDE + mi];
                float2 v3 = As[(k8 + tg + 4) * ASTRIDE + mi + 8];
                ah[mf][0] = __float_as_uint(v0.x); al[mf][0] = __float_as_uint(v0.y);
                ah[mf][1] = __float_as_uint(v1.x); al[mf][1] = __float_as_uint(v1.y);
                ah[mf][2] = __float_as_uint(v2.x); al[mf][2] = __float_as_uint(v2.y);
                ah[mf][3] = __float_as_uint(v3.x); al[mf][3] = __float_as_uint(v3.y);
            }
#pragma unroll
            for (int nf = 0; nf < 4; nf++) {
                int ni = n0w + nf * 8 + g;
                bh[nf][0] = __float_as_uint(Bs[(k8 + tg) * BSTRIDE + ni]);
                bh[nf][1] = __float_as_uint(Bs[(k8 + tg + 4) * BSTRIDE + ni]);
            }
#pragma unroll
            for (int mf = 0; mf < 4; mf++)
#pragma unroll
                for (int nf = 0; nf < 4; nf++) {
                    mma8(c[mf][nf], ah[mf], bh[nf]);
                    mma8(c[mf][nf], al[mf], bh[nf]);
                }
        }
        __syncthreads();
    }

#pragma unroll
    for (int mf = 0; mf < 4; mf++) {
#pragma unroll
        for (int nf = 0; nf < 4; nf++) {
            int col = colBlock + n0w + nf * 8 + 2 * tg;
            float2 bv = *(const float2*)(bias + col);
            int r0 = rowBlock + m0w + mf * 16 + g;
            *(float2*)(C + (size_t)r0 * DM + col) =
                make_float2(c[mf][nf][0] + bv.x, c[mf][nf][1] + bv.y);
            *(float2*)(C + (size_t)(r0 + 8) * DM + col) =
                make_float2(c[mf][nf][2] + bv.x, c[mf][nf][3] + bv.y);
        }
    }
}

// ---------------------------------------------------------------------------
// Flash attention, tf32 mma, register-resident softmax (no score roundtrip).
// Block = 128 threads (4 warps); warp w owns query rows [w*16, w*16+16).
// ---------------------------------------------------------------------------
#define QKS 68   // qs/ks float row stride (conflict-free for along-k frags)
#define VST 72   // vs float row stride (conflict-free for along-s frags)

__global__ __launch_bounds__(128) void attn_mma_kernel(
    const float* __restrict__ qg, const float* __restrict__ kg,
    const float* __restrict__ vg, float* __restrict__ ctx)
{
    extern __shared__ float smf[];
    float* qs = smf;               // [64][QKS]
    float* ks = qs + 64 * QKS;     // [64][QKS]
    float* vs = ks + 64 * QKS;     // [64][VST]

    const int tid  = threadIdx.x;
    const int lane = tid & 31;
    const int warp = tid >> 5;
    const int g  = lane >> 2;
    const int tg = lane & 3;
    const int w16 = warp * 16;
    const int b = blockIdx.y >> 4;
    const int h = blockIdx.y & 15;
    const int q0 = blockIdx.x * 64;
    const float scale = 0.125f;      // 1/sqrt(64)

    const int lr = tid >> 1;             // 0..63
    const int lc = (tid & 1) * 32;

    // Load Q (scaled, tf32-rounded)
    const float* qbase = qg + (size_t)(b * LSEQ + q0) * DM + h * HD;
#pragma unroll
    for (int i = 0; i < 8; i++) {
        float4 v4 = *(const float4*)(qbase + (size_t)lr * DM + lc + 4 * i);
        float4 t;
        t.x = tf32f(v4.x * scale);
        t.y = tf32f(v4.y * scale);
        t.z = tf32f(v4.z * scale);
        t.w = tf32f(v4.w * scale);
        *(float4*)(qs + lr * QKS + lc + 4 * i) = t;
    }

    float m0 = -1e30f, m1 = -1e30f, l0 = 0.f, l1 = 0.f;
    float o[8][4];
#pragma unroll
    for (int nf = 0; nf < 8; nf++)
#pragma unroll
        for (int i = 0; i < 4; i++) o[nf][i] = 0.f;

    const float* kbase = kg + (size_t)(b * LSEQ) * DM + h * HD;
    const float* vbase = vg + (size_t)(b * LSEQ) * DM + h * HD;
    const unsigned FULL = 0xffffffffu;
    const int srcA = (lane & ~3) | (tg >> 1);   // quad-mate holding col tg
    const int srcB = srcA + 2;                  // quad-mate holding col tg+4

    for (int s0 = 0; s0 < LSEQ; s0 += 64) {
        __syncthreads();   // previous chunk done reading ks/vs
#pragma unroll
        for (int i = 0; i < 8; i++) {
            float4 k4 = *(const float4*)(kbase + (size_t)(s0 + lr) * DM + lc + 4 * i);
            float4 v4 = *(const float4*)(vbase + (size_t)(s0 + lr) * DM + lc + 4 * i);
            float4 tk, tv;
            tk.x = tf32f(k4.x); tv.x = tf32f(v4.x);
            tk.y = tf32f(k4.y); tv.y = tf32f(v4.y);
            tk.z = tf32f(k4.z); tv.z = tf32f(v4.z);
            tk.w = tf32f(k4.w); tv.w = tf32f(v4.w);
            *(float4*)(ks + lr * QKS + lc + 4 * i) = tk;
            *(float4*)(vs + lr * VST + lc + 4 * i) = tv;
        }
        __syncthreads();

        // --- scores: S = Q · K^T (rows w16..w16+15, cols s0..s0+63) ---
        float sc[8][4];
#pragma unroll
        for (int nf = 0; nf < 8; nf++)
#pragma unroll
            for (int i = 0; i < 4; i++) sc[nf][i] = 0.f;

#pragma unroll
        for (int k8 = 0; k8 < 64; k8 += 8) {
            unsigned a[4];
            const float* qr0 = qs + (w16 + g) * QKS + k8 + tg;
            const float* qr1 = qs + (w16 + g + 8) * QKS + k8 + tg;
            a[0] = __float_as_uint(qr0[0]);
            a[1] = __float_as_uint(qr1[0]);
            a[2] = __float_as_uint(qr0[4]);
            a[3] = __float_as_uint(qr1[4]);
#pragma unroll
            for (int nf = 0; nf < 8; nf++) {
                unsigned bb[2];
                const float* kr = ks + (nf * 8 + g) * QKS + k8 + tg;
                bb[0] = __float_as_uint(kr[0]);
                bb[1] = __float_as_uint(kr[4]);
                mma8(sc[nf], a, bb);
            }
        }

        // --- register softmax (row w16+g in sc[*][0,1], row w16+g+8 in [2,3]) ---
        float mx0 = -1e30f, mx1 = -1e30f;
#pragma unroll
        for (int nf = 0; nf < 8; nf++) {
            mx0 = fmaxf(mx0, fmaxf(sc[nf][0], sc[nf][1]));
            mx1 = fmaxf(mx1, fmaxf(sc[nf][2], sc[nf][3]));
        }
        mx0 = fmaxf(mx0, __shfl_xor_sync(FULL, mx0, 1));
        mx0 = fmaxf(mx0, __shfl_xor_sync(FULL, mx0, 2));
        mx1 = fmaxf(mx1, __shfl_xor_sync(FULL, mx1, 1));
        mx1 = fmaxf(mx1, __shfl_xor_sync(FULL, mx1, 2));
        float m0n = fmaxf(m0, mx0);
        float m1n = fmaxf(m1, mx1);
        float al0 = __expf(m0 - m0n);
        float al1 = __expf(m1 - m1n);
        float rs0 = 0.f, rs1 = 0.f;
#pragma unroll
        for (int nf = 0; nf < 8; nf++) {
            float p0 = tf32f(__expf(sc[nf][0] - m0n));
            float p1 = tf32f(__expf(sc[nf][1] - m0n));
            float p2 = tf32f(__expf(sc[nf][2] - m1n));
            float p3 = tf32f(__expf(sc[nf][3] - m1n));
            sc[nf][0] = p0; sc[nf][1] = p1; sc[nf][2] = p2; sc[nf][3] = p3;
            rs0 += p0 + p1;
            rs1 += p2 + p3;
        }
        rs0 += __shfl_xor_sync(FULL, rs0, 1);
        rs0 += __shfl_xor_sync(FULL, rs0, 2);
        rs1 += __shfl_xor_sync(FULL, rs1, 1);
        rs1 += __shfl_xor_sync(FULL, rs1, 2);
        l0 = l0 * al0 + rs0;
        l1 = l1 * al1 + rs1;
        m0 = m0n;
        m1 = m1n;

#pragma unroll
        for (int nf = 0; nf < 8; nf++) {
            o[nf][0] *= al0; o[nf][1] *= al0;
            o[nf][2] *= al1; o[nf][3] *= al1;
        }

        // --- P·V: A-fragments from registers via quad shuffles ---
#pragma unroll
        for (int j = 0; j < 8; j++) {
            float f00 = __shfl_sync(FULL, sc[j][0], srcA);
            float f01 = __shfl_sync(FULL, sc[j][1], srcA);
            float f10 = __shfl_sync(FULL, sc[j][2], srcA);
            float f11 = __shfl_sync(FULL, sc[j][3], srcA);
            float f20 = __shfl_sync(FULL, sc[j][0], srcB);
            float f21 = __shfl_sync(FULL, sc[j][1], srcB);
            float f30 = __shfl_sync(FULL, sc[j][2], srcB);
            float f31 = __shfl_sync(FULL, sc[j][3], srcB);
            unsigned a[4];
            a[0] = __float_as_uint((tg & 1) ? f01 : f00);  // P[g][j8+tg]
            a[1] = __float_as_uint((tg & 1) ? f11 : f10);  // P[g+8][j8+tg]
            a[2] = __float_as_uint((tg & 1) ? f21 : f20);  // P[g][j8+tg+4]
            a[3] = __float_as_uint((tg & 1) ? f31 : f30);  // P[g+8][j8+tg+4]
#pragma unroll
            for (int nf = 0; nf < 8; nf++) {
                unsigned bb[2];
                const float* vr = vs + (j * 8 + tg) * VST + nf * 8 + g;
                bb[0] = __float_as_uint(vr[0]);
                bb[1] = __float_as_uint(vr[4 * VST]);
                mma8(o[nf], a, bb);
            }
        }
    }

    // final normalize + write ctx
    float inv0 = 1.f / l0;
    float inv1 = 1.f / l1;
    float* cb0 = ctx + (size_t)(b * LSEQ + q0 + w16 + g) * DM + h * HD;
    float* cb1 = ctx + (size_t)(b * LSEQ + q0 + w16 + g + 8) * DM + h * HD;
#pragma unroll
    for (int nf = 0; nf < 8; nf++) {
        *(float2*)(cb0 + nf * 8 + 2 * tg) =
            make_float2(o[nf][0] * inv0, o[nf][1] * inv0);
        *(float2*)(cb1 + nf * 8 + 2 * tg) =
            make_float2(o[nf][2] * inv1, o[nf][3] * inv1);
    }
}

// ---------------------------------------------------------------------------
extern "C" void kernel_launch(void* const* d_in, const int* in_sizes, int n_in,
                              void* d_out, int out_size)
{
    const float* queries = (const float*)d_in[0];
    const float* keys    = (const float*)d_in[1];
    const float* values  = (const float*)d_in[2];
    const float* Wq      = (const float*)d_in[3];
    const float* bq      = (const float*)d_in[4];
    const float* Wk      = (const float*)d_in[5];
    const float* bk      = (const float*)d_in[6];
    const float* Wv      = (const float*)d_in[7];
    const float* bv      = (const float*)d_in[8];
    const float* Wo      = (const float*)d_in[9];
    const float* bo      = (const float*)d_in[10];
    float* out = (float*)d_out;

    float *qb, *kb, *vb, *cb;
    cudaGetSymbolAddress((void**)&qb, g_q);
    cudaGetSymbolAddress((void**)&kb, g_k);
    cudaGetSymbolAddress((void**)&vb, g_v);
    cudaGetSymbolAddress((void**)&cb, g_ctx);

    const size_t gemm_sm = 32 * ASTRIDE * sizeof(float2) + 32 * BSTRIDE * sizeof(float);
    const size_t attn_sm = (size_t)(64 * QKS * 2 + 64 * VST) * sizeof(float);

    cudaFuncSetAttribute(gemm_tf32x2_kernel,
                         cudaFuncAttributeMaxDynamicSharedMemorySize, (int)gemm_sm);
    cudaFuncSetAttribute(attn_mma_kernel,
                         cudaFuncAttributeMaxDynamicSharedMemorySize, (int)attn_sm);

    dim3 ggrid(DM / 128, MROWS / 128);
    gemm_tf32x2_kernel<<<ggrid, 256, gemm_sm>>>(queries, Wq, bq, qb);
    gemm_tf32x2_kernel<<<ggrid, 256, gemm_sm>>>(keys,    Wk, bk, kb);
    gemm_tf32x2_kernel<<<ggrid, 256, gemm_sm>>>(values,  Wv, bv, vb);

    attn_mma_kernel<<<dim3(LSEQ / 64, BSZ * NH), 128, attn_sm>>>(qb, kb, vb, cb);

    gemm_tf32x2_kernel<<<ggrid, 256, gemm_sm>>>(cb, Wo, bo, out);
}

// round 4
// speedup vs baseline: 2.4420x; 1.6808x over previous
#include <cuda_runtime.h>
#include <cuda_bf16.h>

#define BSZ   4
#define LSEQ  2048
#define DM    1024
#define NH    16
#define HD    64
#define MROWS (BSZ * LSEQ)   // 8192

__device__ float g_q[MROWS * DM];
__device__ float g_k[MROWS * DM];
__device__ float g_v[MROWS * DM];
__device__ float g_ctx[MROWS * DM];

__device__ __forceinline__ unsigned tf32_rna(float x) {
    unsigned u;
    asm("cvt.rna.tf32.f32 %0, %1;" : "=r"(u) : "f"(x));
    return u;
}
__device__ __forceinline__ float tf32f(float x) {
    return __uint_as_float(tf32_rna(x));
}

__device__ __forceinline__ void mma8(float* c, const unsigned* a, const unsigned* b) {
    asm volatile(
        "mma.sync.aligned.m16n8k8.row.col.f32.tf32.tf32.f32 "
        "{%0,%1,%2,%3}, {%4,%5,%6,%7}, {%8,%9}, {%0,%1,%2,%3};\n"
        : "+f"(c[0]), "+f"(c[1]), "+f"(c[2]), "+f"(c[3])
        : "r"(a[0]), "r"(a[1]), "r"(a[2]), "r"(a[3]),
          "r"(b[0]), "r"(b[1]));
}

__device__ __forceinline__ void mma16bf(float* c, const unsigned* a, const unsigned* b) {
    asm volatile(
        "mma.sync.aligned.m16n8k16.row.col.f32.bf16.bf16.f32 "
        "{%0,%1,%2,%3}, {%4,%5,%6,%7}, {%8,%9}, {%0,%1,%2,%3};\n"
        : "+f"(c[0]), "+f"(c[1]), "+f"(c[2]), "+f"(c[3])
        : "r"(a[0]), "r"(a[1]), "r"(a[2]), "r"(a[3]),
          "r"(b[0]), "r"(b[1]));
}

// pack two floats (k-even=lo halfword, k-odd=hi halfword) as bf16x2, plus residuals
__device__ __forceinline__ void split_pack(float x0, float x1,
                                           unsigned& hi, unsigned& lo) {
    __nv_bfloat16 h0 = __float2bfloat16(x0);
    __nv_bfloat16 h1 = __float2bfloat16(x1);
    __nv_bfloat16 l0 = __float2bfloat16(x0 - __bfloat162float(h0));
    __nv_bfloat16 l1 = __float2bfloat16(x1 - __bfloat162float(h1));
    hi = (unsigned)__bfloat16_as_ushort(h0) |
         ((unsigned)__bfloat16_as_ushort(h1) << 16);
    lo = (unsigned)__bfloat16_as_ushort(l0) |
         ((unsigned)__bfloat16_as_ushort(l1) << 16);
}

// ---------------------------------------------------------------------------
// bf16x2 split GEMM (A=hi+lo, B=hi+lo, 3 passes): C = A @ W + bias
// BM=BN=128, BK=32 (16 k-pairs), 256 threads (8 warps, 2x4), warp tile 64x32.
// ---------------------------------------------------------------------------
#define KP    16     // k-pairs per BK
#define PSTR  136    // u32 stride per k-pair row (128 + 8, conflict-free frags)

__global__ __launch_bounds__(256) void gemm_bf16x2_kernel(
    const float* __restrict__ A, const float* __restrict__ W,
    const float* __restrict__ bias, float* __restrict__ C)
{
    extern __shared__ unsigned smu[];
    unsigned* Ah = smu;                 // [KP][PSTR]
    unsigned* Al = Ah + KP * PSTR;
    unsigned* Bh = Al + KP * PSTR;
    unsigned* Bl = Bh + KP * PSTR;

    const int tid  = threadIdx.x;
    const int lane = tid & 31;
    const int warp = tid >> 5;
    const int g  = lane >> 2;
    const int tg = lane & 3;
    const int m0w = (warp & 1) * 64;
    const int n0w = (warp >> 1) * 32;
    const int rowBlock = blockIdx.y * 128;
    const int colBlock = blockIdx.x * 128;

    // A staging: thread -> row (tid>>1), 16 consecutive k at (tid&1)*16
    const int arow = tid >> 1;
    const int acb  = (tid & 1) * 16;
    const int acp  = (tid & 1) * 8;     // k-pair offset
    // B staging: thread -> k-pair (tid>>4), 8 n at (tid&15)*8
    const int bkp  = tid >> 4;
    const int bnc  = (tid & 15) * 8;

    const float* Ap  = A + (size_t)(rowBlock + arow) * DM + acb;
    const float* Wp0 = W + (size_t)(2 * bkp) * DM + colBlock + bnc;
    const float* Wp1 = W + (size_t)(2 * bkp + 1) * DM + colBlock + bnc;

    float4 pa[4], pb0[2], pb1[2];
#pragma unroll
    for (int i = 0; i < 4; i++) pa[i] = *(const float4*)(Ap + 4 * i);
#pragma unroll
    for (int i = 0; i < 2; i++) {
        pb0[i] = *(const float4*)(Wp0 + 4 * i);
        pb1[i] = *(const float4*)(Wp1 + 4 * i);
    }

    float c[4][4][4];
#pragma unroll
    for (int mf = 0; mf < 4; mf++)
#pragma unroll
        for (int nf = 0; nf < 4; nf++)
#pragma unroll
            for (int i = 0; i < 4; i++) c[mf][nf][i] = 0.f;

    for (int kt = 0; kt < 32; kt++) {
        // --- stage (split hi/lo, pack k-pairs) ---
#pragma unroll
        for (int i = 0; i < 4; i++) {
            unsigned h, l;
            split_pack(((const float*)&pa[i])[0], ((const float*)&pa[i])[1], h, l);
            Ah[(acp + 2 * i) * PSTR + arow] = h;
            Al[(acp + 2 * i) * PSTR + arow] = l;
            split_pack(((const float*)&pa[i])[2], ((const float*)&pa[i])[3], h, l);
            Ah[(acp + 2 * i + 1) * PSTR + arow] = h;
            Al[(acp + 2 * i + 1) * PSTR + arow] = l;
        }
#pragma unroll
        for (int i = 0; i < 2; i++) {
            const float* r0 = (const float*)&pb0[i];
            const float* r1 = (const float*)&pb1[i];
#pragma unroll
            for (int j = 0; j < 4; j++) {
                unsigned h, l;
                split_pack(r0[j], r1[j], h, l);   // lo = k even row
                Bh[bkp * PSTR + bnc + 4 * i + j] = h;
                Bl[bkp * PSTR + bnc + 4 * i + j] = l;
            }
        }
        __syncthreads();

        if (kt < 31) {
            const float* Ap2  = Ap + (kt + 1) * 32;
            const float* Wp02 = Wp0 + (size_t)(kt + 1) * 32 * DM;
            const float* Wp12 = Wp1 + (size_t)(kt + 1) * 32 * DM;
#pragma unroll
            for (int i = 0; i < 4; i++) pa[i] = *(const float4*)(Ap2 + 4 * i);
#pragma unroll
            for (int i = 0; i < 2; i++) {
                pb0[i] = *(const float4*)(Wp02 + 4 * i);
                pb1[i] = *(const float4*)(Wp12 + 4 * i);
            }
        }

#pragma unroll
        for (int s = 0; s < 2; s++) {
            const int p8 = s * 8;
            unsigned ah[4][4], al[4][4], bh[4][2], bl[4][2];
#pragma unroll
            for (int mf = 0; mf < 4; mf++) {
                int mi = m0w + mf * 16 + g;
                ah[mf][0] = Ah[(p8 + tg) * PSTR + mi];
                ah[mf][1] = Ah[(p8 + tg) * PSTR + mi + 8];
                ah[mf][2] = Ah[(p8 + tg + 4) * PSTR + mi];
                ah[mf][3] = Ah[(p8 + tg + 4) * PSTR + mi + 8];
                al[mf][0] = Al[(p8 + tg) * PSTR + mi];
                al[mf][1] = Al[(p8 + tg) * PSTR + mi + 8];
                al[mf][2] = Al[(p8 + tg + 4) * PSTR + mi];
                al[mf][3] = Al[(p8 + tg + 4) * PSTR + mi + 8];
            }
#pragma unroll
            for (int nf = 0; nf < 4; nf++) {
                int ni = n0w + nf * 8 + g;
                bh[nf][0] = Bh[(p8 + tg) * PSTR + ni];
                bh[nf][1] = Bh[(p8 + tg + 4) * PSTR + ni];
                bl[nf][0] = Bl[(p8 + tg) * PSTR + ni];
                bl[nf][1] = Bl[(p8 + tg + 4) * PSTR + ni];
            }
#pragma unroll
            for (int mf = 0; mf < 4; mf++)
#pragma unroll
                for (int nf = 0; nf < 4; nf++) {
                    mma16bf(c[mf][nf], ah[mf], bh[nf]);
                    mma16bf(c[mf][nf], al[mf], bh[nf]);
                    mma16bf(c[mf][nf], ah[mf], bl[nf]);
                }
        }
        __syncthreads();
    }

#pragma unroll
    for (int mf = 0; mf < 4; mf++) {
#pragma unroll
        for (int nf = 0; nf < 4; nf++) {
            int col = colBlock + n0w + nf * 8 + 2 * tg;
            float2 bv = *(const float2*)(bias + col);
            int r0 = rowBlock + m0w + mf * 16 + g;
            *(float2*)(C + (size_t)r0 * DM + col) =
                make_float2(c[mf][nf][0] + bv.x, c[mf][nf][1] + bv.y);
            *(float2*)(C + (size_t)(r0 + 8) * DM + col) =
                make_float2(c[mf][nf][2] + bv.x, c[mf][nf][3] + bv.y);
        }
    }
}

// ---------------------------------------------------------------------------
// Flash attention, tf32 mma, register softmax, 32 q-rows per warp
// (B-fragments shared between the two 16-row groups).
// Block = 128 threads / 4 warps -> 128 query rows per block.
// ---------------------------------------------------------------------------
#define QKS 68
#define VST 72

__global__ __launch_bounds__(128) void attn_mma_kernel(
    const float* __restrict__ qg, const float* __restrict__ kg,
    const float* __restrict__ vg, float* __restrict__ ctx)
{
    extern __shared__ float smf[];
    float* qs = smf;               // [128][QKS]
    float* ks = qs + 128 * QKS;    // [64][QKS]
    float* vs = ks + 64 * QKS;     // [64][VST]

    const int tid  = threadIdx.x;
    const int lane = tid & 31;
    const int warp = tid >> 5;
    const int g  = lane >> 2;
    const int tg = lane & 3;
    const int w32 = warp * 32;
    const int b = blockIdx.y >> 4;
    const int h = blockIdx.y & 15;
    const int q0 = blockIdx.x * 128;
    const float scale = 0.125f;

    // Load Q (scaled, tf32-rounded): 128 rows x 64 cols
    const float* qbase = qg + (size_t)(b * LSEQ + q0) * DM + h * HD;
    for (int p = tid; p < 128 * 16; p += 128) {
        int r  = p >> 4;
        int c4 = (p & 15) << 2;
        float4 v4 = *(const float4*)(qbase + (size_t)r * DM + c4);
        float4 t;
        t.x = tf32f(v4.x * scale);
        t.y = tf32f(v4.y * scale);
        t.z = tf32f(v4.z * scale);
        t.w = tf32f(v4.w * scale);
        *(float4*)(qs + r * QKS + c4) = t;
    }

    float m[4] = {-1e30f, -1e30f, -1e30f, -1e30f};
    float l[4] = {0.f, 0.f, 0.f, 0.f};
    float o0[8][4], o1[8][4];
#pragma unroll
    for (int nf = 0; nf < 8; nf++)
#pragma unroll
        for (int i = 0; i < 4; i++) { o0[nf][i] = 0.f; o1[nf][i] = 0.f; }

    const float* kbase = kg + (size_t)(b * LSEQ) * DM + h * HD;
    const float* vbase = vg + (size_t)(b * LSEQ) * DM + h * HD;
    const unsigned FULL = 0xffffffffu;
    const int srcA = (lane & ~3) | (tg >> 1);
    const int srcB = srcA + 2;

    for (int s0 = 0; s0 < LSEQ; s0 += 64) {
        __syncthreads();
        for (int p = tid; p < 64 * 16; p += 128) {
            int r  = p >> 4;
            int c4 = (p & 15) << 2;
            float4 k4 = *(const float4*)(kbase + (size_t)(s0 + r) * DM + c4);
            float4 v4 = *(const float4*)(vbase + (size_t)(s0 + r) * DM + c4);
            float4 tk, tv;
            tk.x = tf32f(k4.x); tv.x = tf32f(v4.x);
            tk.y = tf32f(k4.y); tv.y = tf32f(v4.y);
            tk.z = tf32f(k4.z); tv.z = tf32f(v4.z);
            tk.w = tf32f(k4.w); tv.w = tf32f(v4.w);
            *(float4*)(ks + r * QKS + c4) = tk;
            *(float4*)(vs + r * VST + c4) = tv;
        }
        __syncthreads();

        // --- scores for both row groups ---
        float sc0[8][4], sc1[8][4];
#pragma unroll
        for (int nf = 0; nf < 8; nf++)
#pragma unroll
            for (int i = 0; i < 4; i++) { sc0[nf][i] = 0.f; sc1[nf][i] = 0.f; }

#pragma unroll
        for (int k8 = 0; k8 < 64; k8 += 8) {
            unsigned a0[4], a1[4];
            const float* q00 = qs + (w32 + g) * QKS + k8 + tg;
            const float* q01 = qs + (w32 + g + 8) * QKS + k8 + tg;
            const float* q10 = qs + (w32 + 16 + g) * QKS + k8 + tg;
            const float* q11 = qs + (w32 + 24 + g) * QKS + k8 + tg;
            a0[0] = __float_as_uint(q00[0]);
            a0[1] = __float_as_uint(q01[0]);
            a0[2] = __float_as_uint(q00[4]);
            a0[3] = __float_as_uint(q01[4]);
            a1[0] = __float_as_uint(q10[0]);
            a1[1] = __float_as_uint(q11[0]);
            a1[2] = __float_as_uint(q10[4]);
            a1[3] = __float_as_uint(q11[4]);
#pragma unroll
            for (int nf = 0; nf < 8; nf++) {
                unsigned bb[2];
                const float* kr = ks + (nf * 8 + g) * QKS + k8 + tg;
                bb[0] = __float_as_uint(kr[0]);
                bb[1] = __float_as_uint(kr[4]);
                mma8(sc0[nf], a0, bb);
                mma8(sc1[nf], a1, bb);
            }
        }

        // --- register softmax (4 rows per thread: g, g+8, 16+g, 24+g) ---
        float mx[4] = {-1e30f, -1e30f, -1e30f, -1e30f};
#pragma unroll
        for (int nf = 0; nf < 8; nf++) {
            mx[0] = fmaxf(mx[0], fmaxf(sc0[nf][0], sc0[nf][1]));
            mx[1] = fmaxf(mx[1], fmaxf(sc0[nf][2], sc0[nf][3]));
            mx[2] = fmaxf(mx[2], fmaxf(sc1[nf][0], sc1[nf][1]));
            mx[3] = fmaxf(mx[3], fmaxf(sc1[nf][2], sc1[nf][3]));
        }
        float al[4], mn[4], rs[4] = {0.f, 0.f, 0.f, 0.f};
#pragma unroll
        for (int r = 0; r < 4; r++) {
            mx[r] = fmaxf(mx[r], __shfl_xor_sync(FULL, mx[r], 1));
            mx[r] = fmaxf(mx[r], __shfl_xor_sync(FULL, mx[r], 2));
            mn[r] = fmaxf(m[r], mx[r]);
            al[r] = __expf(m[r] - mn[r]);
        }
#pragma unroll
        for (int nf = 0; nf < 8; nf++) {
            float p0 = tf32f(__expf(sc0[nf][0] - mn[0]));
            float p1 = tf32f(__expf(sc0[nf][1] - mn[0]));
            float p2 = tf32f(__expf(sc0[nf][2] - mn[1]));
            float p3 = tf32f(__expf(sc0[nf][3] - mn[1]));
            sc0[nf][0] = p0; sc0[nf][1] = p1; sc0[nf][2] = p2; sc0[nf][3] = p3;
            rs[0] += p0 + p1; rs[1] += p2 + p3;
            p0 = tf32f(__expf(sc1[nf][0] - mn[2]));
            p1 = tf32f(__expf(sc1[nf][1] - mn[2]));
            p2 = tf32f(__expf(sc1[nf][2] - mn[3]));
            p3 = tf32f(__expf(sc1[nf][3] - mn[3]));
            sc1[nf][0] = p0; sc1[nf][1] = p1; sc1[nf][2] = p2; sc1[nf][3] = p3;
            rs[2] += p0 + p1; rs[3] += p2 + p3;
        }
#pragma unroll
        for (int r = 0; r < 4; r++) {
            rs[r] += __shfl_xor_sync(FULL, rs[r], 1);
            rs[r] += __shfl_xor_sync(FULL, rs[r], 2);
            l[r] = l[r] * al[r] + rs[r];
            m[r] = mn[r];
        }

#pragma unroll
        for (int nf = 0; nf < 8; nf++) {
            o0[nf][0] *= al[0]; o0[nf][1] *= al[0];
            o0[nf][2] *= al[1]; o0[nf][3] *= al[1];
            o1[nf][0] *= al[2]; o1[nf][1] *= al[2];
            o1[nf][2] *= al[3]; o1[nf][3] *= al[3];
        }

        // --- P·V: A-frags via quad shuffles, B-frags shared between groups ---
#pragma unroll
        for (int j = 0; j < 8; j++) {
            unsigned a0[4], a1[4];
            {
                float f00 = __shfl_sync(FULL, sc0[j][0], srcA);
                float f01 = __shfl_sync(FULL, sc0[j][1], srcA);
                float f10 = __shfl_sync(FULL, sc0[j][2], srcA);
                float f11 = __shfl_sync(FULL, sc0[j][3], srcA);
                float f20 = __shfl_sync(FULL, sc0[j][0], srcB);
                float f21 = __shfl_sync(FULL, sc0[j][1], srcB);
                float f30 = __shfl_sync(FULL, sc0[j][2], srcB);
                float f31 = __shfl_sync(FULL, sc0[j][3], srcB);
                a0[0] = __float_as_uint((tg & 1) ? f01 : f00);
                a0[1] = __float_as_uint((tg & 1) ? f11 : f10);
                a0[2] = __float_as_uint((tg & 1) ? f21 : f20);
                a0[3] = __float_as_uint((tg & 1) ? f31 : f30);
            }
            {
                float f00 = __shfl_sync(FULL, sc1[j][0], srcA);
                float f01 = __shfl_sync(FULL, sc1[j][1], srcA);
                float f10 = __shfl_sync(FULL, sc1[j][2], srcA);
                float f11 = __shfl_sync(FULL, sc1[j][3], srcA);
                float f20 = __shfl_sync(FULL, sc1[j][0], srcB);
                float f21 = __shfl_sync(FULL, sc1[j][1], srcB);
                float f30 = __shfl_sync(FULL, sc1[j][2], srcB);
                float f31 = __shfl_sync(FULL, sc1[j][3], srcB);
                a1[0] = __float_as_uint((tg & 1) ? f01 : f00);
                a1[1] = __float_as_uint((tg & 1) ? f11 : f10);
                a1[2] = __float_as_uint((tg & 1) ? f21 : f20);
                a1[3] = __float_as_uint((tg & 1) ? f31 : f30);
            }
#pragma unroll
            for (int nf = 0; nf < 8; nf++) {
                unsigned bb[2];
                const float* vr = vs + (j * 8 + tg) * VST + nf * 8 + g;
                bb[0] = __float_as_uint(vr[0]);
                bb[1] = __float_as_uint(vr[4 * VST]);
                mma8(o0[nf], a0, bb);
                mma8(o1[nf], a1, bb);
            }
        }
    }

    // final normalize + write ctx (4 rows)
    float inv[4];
#pragma unroll
    for (int r = 0; r < 4; r++) inv[r] = 1.f / l[r];
    const int rowOff[4] = {0, 8, 16, 24};
    float* base = ctx + (size_t)(b * LSEQ + q0 + w32 + g) * DM + h * HD;
#pragma unroll
    for (int r = 0; r < 4; r++) {
        float* cb = base + (size_t)rowOff[r] * DM;
        float (*oo)[4] = (r < 2) ? o0 : o1;
        int i0 = (r & 1) ? 2 : 0;
#pragma unroll
        for (int nf = 0; nf < 8; nf++) {
            *(float2*)(cb + nf * 8 + 2 * tg) =
                make_float2(oo[nf][i0] * inv[r], oo[nf][i0 + 1] * inv[r]);
        }
    }
}

// ---------------------------------------------------------------------------
extern "C" void kernel_launch(void* const* d_in, const int* in_sizes, int n_in,
                              void* d_out, int out_size)
{
    const float* queries = (const float*)d_in[0];
    const float* keys    = (const float*)d_in[1];
    const float* values  = (const float*)d_in[2];
    const float* Wq      = (const float*)d_in[3];
    const float* bq      = (const float*)d_in[4];
    const float* Wk      = (const float*)d_in[5];
    const float* bk      = (const float*)d_in[6];
    const float* Wv      = (const float*)d_in[7];
    const float* bv      = (const float*)d_in[8];
    const float* Wo      = (const float*)d_in[9];
    const float* bo      = (const float*)d_in[10];
    float* out = (float*)d_out;

    float *qb, *kb, *vb, *cb;
    cudaGetSymbolAddress((void**)&qb, g_q);
    cudaGetSymbolAddress((void**)&kb, g_k);
    cudaGetSymbolAddress((void**)&vb, g_v);
    cudaGetSymbolAddress((void**)&cb, g_ctx);

    const size_t gemm_sm = (size_t)4 * KP * PSTR * sizeof(unsigned);          // 34816
    const size_t attn_sm = (size_t)(128 * QKS + 64 * QKS + 64 * VST) * sizeof(float);

    cudaFuncSetAttribute(gemm_bf16x2_kernel,
                         cudaFuncAttributeMaxDynamicSharedMemorySize, (int)gemm_sm);
    cudaFuncSetAttribute(attn_mma_kernel,
                         cudaFuncAttributeMaxDynamicSharedMemorySize, (int)attn_sm);

    dim3 ggrid(DM / 128, MROWS / 128);
    gemm_bf16x2_kernel<<<ggrid, 256, gemm_sm>>>(queries, Wq, bq, qb);
    gemm_bf16x2_kernel<<<ggrid, 256, gemm_sm>>>(keys,    Wk, bk, kb);
    gemm_bf16x2_kernel<<<ggrid, 256, gemm_sm>>>(values,  Wv, bv, vb);

    attn_mma_kernel<<<dim3(LSEQ / 128, BSZ * NH), 128, attn_sm>>>(qb, kb, vb, cb);

    gemm_bf16x2_kernel<<<ggrid, 256, gemm_sm>>>(cb, Wo, bo, out);
}

// round 6
// speedup vs baseline: 3.6954x; 1.5132x over previous
#include <cuda_runtime.h>
#include <cuda_bf16.h>
#include <cstdint>

#define BSZ   4
#define LSEQ  2048
#define DM    1024
#define NH    16
#define HD    64
#define MROWS (BSZ * LSEQ)   // 8192
#define KHALF 512            // DM/2 (k-pairs)

// Scratch (device globals — no allocation allowed)
__device__ float g_q[MROWS * DM];
__device__ float g_k[MROWS * DM];
__device__ float g_v[MROWS * DM];
__device__ float g_ctx[MROWS * DM];
__device__ uint32_t g_pa_h[MROWS * KHALF];
__device__ uint32_t g_pa_l[MROWS * KHALF];
__device__ uint32_t g_pw_h[KHALF * DM];
__device__ uint32_t g_pw_l[KHALF * DM];

// ---------------------------------------------------------------------------
// helpers
// ---------------------------------------------------------------------------
__device__ __forceinline__ uint32_t smem_u32(const void* p) {
    uint32_t a;
    asm("{ .reg .u64 t; cvta.to.shared.u64 t, %1; cvt.u32.u64 %0, t; }"
        : "=r"(a) : "l"(p));
    return a;
}
__device__ __forceinline__ void cp16(uint32_t dst, const void* src) {
    asm volatile("cp.async.cg.shared.global [%0], [%1], 16;"
                 :: "r"(dst), "l"(src));
}
#define CP_COMMIT() asm volatile("cp.async.commit_group;" ::: "memory")
#define CP_WAIT0()  asm volatile("cp.async.wait_group 0;" ::: "memory")
#define CP_WAIT1()  asm volatile("cp.async.wait_group 1;" ::: "memory")
#define LDSM4(r0, r1, r2, r3, addr) \
    asm volatile("ldmatrix.sync.aligned.m8n8.x4.shared.b16 {%0,%1,%2,%3}, [%4];" \
                 : "=r"(r0), "=r"(r1), "=r"(r2), "=r"(r3) : "r"(addr))

__device__ __forceinline__ unsigned tf32_rna(float x) {
    unsigned u;
    asm("cvt.rna.tf32.f32 %0, %1;" : "=r"(u) : "f"(x));
    return u;
}
__device__ __forceinline__ float tf32f(float x) {
    return __uint_as_float(tf32_rna(x));
}
__device__ __forceinline__ void mma8(float* c, const unsigned* a, const unsigned* b) {
    asm volatile(
        "mma.sync.aligned.m16n8k8.row.col.f32.tf32.tf32.f32 "
        "{%0,%1,%2,%3}, {%4,%5,%6,%7}, {%8,%9}, {%0,%1,%2,%3};\n"
        : "+f"(c[0]), "+f"(c[1]), "+f"(c[2]), "+f"(c[3])
        : "r"(a[0]), "r"(a[1]), "r"(a[2]), "r"(a[3]),
          "r"(b[0]), "r"(b[1]));
}
__device__ __forceinline__ void mma16bf(float* c, const unsigned* a, const unsigned* b) {
    asm volatile(
        "mma.sync.aligned.m16n8k16.row.col.f32.bf16.bf16.f32 "
        "{%0,%1,%2,%3}, {%4,%5,%6,%7}, {%8,%9}, {%0,%1,%2,%3};\n"
        : "+f"(c[0]), "+f"(c[1]), "+f"(c[2]), "+f"(c[3])
        : "r"(a[0]), "r"(a[1]), "r"(a[2]), "r"(a[3]),
          "r"(b[0]), "r"(b[1]));
}
__device__ __forceinline__ void split_pack(float x0, float x1,
                                           unsigned& hi, unsigned& lo) {
    __nv_bfloat16 h0 = __float2bfloat16(x0);
    __nv_bfloat16 h1 = __float2bfloat16(x1);
    __nv_bfloat16 l0 = __float2bfloat16(x0 - __bfloat162float(h0));
    __nv_bfloat16 l1 = __float2bfloat16(x1 - __bfloat162float(h1));
    hi = (unsigned)__bfloat16_as_ushort(h0) |
         ((unsigned)__bfloat16_as_ushort(h1) << 16);
    lo = (unsigned)__bfloat16_as_ushort(l0) |
         ((unsigned)__bfloat16_as_ushort(l1) << 16);
}

// ---------------------------------------------------------------------------
// pack kernels: fp32 -> split bf16 (hi, lo), k-pair packed
// ---------------------------------------------------------------------------
__global__ __launch_bounds__(256) void pack_a_kernel(
    const float* __restrict__ src, uint32_t* __restrict__ hi,
    uint32_t* __restrict__ lo)
{
    int i = blockIdx.x * 256 + threadIdx.x;   // over MROWS*DM/4
    float4 v = ((const float4*)src)[i];
    unsigned h0, l0, h1, l1;
    split_pack(v.x, v.y, h0, l0);
    split_pack(v.z, v.w, h1, l1);
    hi[2 * i]     = h0;
    hi[2 * i + 1] = h1;
    lo[2 * i]     = l0;
    lo[2 * i + 1] = l1;
}

__global__ __launch_bounds__(256) void pack_w_kernel(
    const float* __restrict__ W, uint32_t* __restrict__ hi,
    uint32_t* __restrict__ lo)
{
    int i = blockIdx.x * 256 + threadIdx.x;   // over KHALF * DM/4
    int kp = i >> 8;
    int j  = (i & 255) * 4;
    float4 r0 = *(const float4*)(W + (size_t)(2 * kp) * DM + j);
    float4 r1 = *(const float4*)(W + (size_t)(2 * kp + 1) * DM + j);
    const float* a = (const float*)&r0;
    const float* b = (const float*)&r1;
#pragma unroll
    for (int t = 0; t < 4; t++) {
        unsigned h, l;
        split_pack(a[t], b[t], h, l);
        hi[(size_t)kp * DM + j + t] = h;
        lo[(size_t)kp * DM + j + t] = l;
    }
}

// ---------------------------------------------------------------------------
// bf16x3 GEMM with packed inputs + cp.async double buffering + ldmatrix.
// BM=BN=128, BK=32 (16 kp), 256 threads (8 warps, 2x4), warp tile 64x32.
// A shared: [m 128][kp 16] stride 20 words; B shared: [kp 16][n 128] stride 136.
// mode: 0 = plain, 1 = tf32 round, 2 = tf32 round of x*0.125*log2(e)  (Q)
// ---------------------------------------------------------------------------
#define ASTR   20
#define BSTR   136
#define OFF_AH 0
#define OFF_AL 10240
#define OFF_BH 20480
#define OFF_BL 29184
#define BUFSZ  38912
#define QSCALE 0.1803368867f   // 0.125 * log2(e)

__device__ __forceinline__ void gemm_prefetch(
    uint32_t sb, const uint32_t* __restrict__ Ah_g,
    const uint32_t* __restrict__ Al_g, const uint32_t* __restrict__ Wh_g,
    const uint32_t* __restrict__ Wl_g, int tid, int rowBlock, int colBlock, int kt)
{
#pragma unroll
    for (int i = 0; i < 2; i++) {
        int c = tid + i * 256;
        int row = c >> 2, cc = c & 3;
        size_t aoff = (size_t)(rowBlock + row) * KHALF + kt * 16 + cc * 4;
        cp16(sb + OFF_AH + row * 80 + cc * 16, Ah_g + aoff);
        cp16(sb + OFF_AL + row * 80 + cc * 16, Al_g + aoff);
        int kp = c >> 5, nc = c & 31;
        size_t boff = (size_t)(kt * 16 + kp) * DM + colBlock + nc * 4;
        cp16(sb + OFF_BH + kp * 544 + nc * 16, Wh_g + boff);
        cp16(sb + OFF_BL + kp * 544 + nc * 16, Wl_g + boff);
    }
}

__global__ __launch_bounds__(256) void gemm_bf16x3_kernel(
    const uint32_t* __restrict__ Ah_g, const uint32_t* __restrict__ Al_g,
    const uint32_t* __restrict__ Wh_g, const uint32_t* __restrict__ Wl_g,
    const float* __restrict__ bias, float* __restrict__ C, int mode)
{
    extern __shared__ char smem[];
    const uint32_t sbase = smem_u32(smem);
    unsigned* smw = (unsigned*)smem;

    const int tid  = threadIdx.x;
    const int lane = tid & 31;
    const int warp = tid >> 5;
    const int g  = lane >> 2;
    const int tg = lane & 3;
    const int m0w = (warp & 1) * 64;
    const int n0w = (warp >> 1) * 32;
    const int rowBlock = blockIdx.y * 128;
    const int colBlock = blockIdx.x * 128;

    // ldmatrix lane->row mapping
    const int rbase = m0w + (lane & 7) + ((lane >> 3) & 1) * 8;
    const int koff  = (lane >> 4) * 4;

    float c[4][4][4];
#pragma unroll
    for (int mf = 0; mf < 4; mf++)
#pragma unroll
        for (int nf = 0; nf < 4; nf++)
#pragma unroll
            for (int i = 0; i < 4; i++) c[mf][nf][i] = 0.f;

    gemm_prefetch(sbase, Ah_g, Al_g, Wh_g, Wl_g, tid, rowBlock, colBlock, 0);
    CP_COMMIT();

    for (int kt = 0; kt < 32; kt++) {
        if (kt < 31) {
            gemm_prefetch(sbase + ((kt + 1) & 1) * BUFSZ, Ah_g, Al_g, Wh_g, Wl_g,
                          tid, rowBlock, colBlock, kt + 1);
            CP_COMMIT();
            CP_WAIT1();
        } else {
            CP_WAIT0();
        }
        __syncthreads();

        const uint32_t ab = sbase + (kt & 1) * BUFSZ;
        unsigned* bh_s = smw + ((kt & 1) * BUFSZ + OFF_BH) / 4;
        unsigned* bl_s = smw + ((kt & 1) * BUFSZ + OFF_BL) / 4;

#pragma unroll
        for (int s = 0; s < 2; s++) {
            const int p8 = s * 8;
            unsigned ah[4][4], al[4][4], bh[4][2], bl[4][2];
#pragma unroll
            for (int mf = 0; mf < 4; mf++) {
                uint32_t ra = ab + OFF_AH +
                    ((uint32_t)((rbase + mf * 16) * ASTR + p8 + koff) << 2);
                LDSM4(ah[mf][0], ah[mf][1], ah[mf][2], ah[mf][3], ra);
                uint32_t rl = ra + (OFF_AL - OFF_AH);
                LDSM4(al[mf][0], al[mf][1], al[mf][2], al[mf][3], rl);
            }
#pragma unroll
            for (int nf = 0; nf < 4; nf++) {
                int ni = n0w + nf * 8 + g;
                bh[nf][0] = bh_s[(p8 + tg) * BSTR + ni];
                bh[nf][1] = bh_s[(p8 + tg + 4) * BSTR + ni];
                bl[nf][0] = bl_s[(p8 + tg) * BSTR + ni];
                bl[nf][1] = bl_s[(p8 + tg + 4) * BSTR + ni];
            }
#pragma unroll
            for (int mf = 0; mf < 4; mf++)
#pragma unroll
                for (int nf = 0; nf < 4; nf++) {
                    mma16bf(c[mf][nf], ah[mf], bh[nf]);
                    mma16bf(c[mf][nf], al[mf], bh[nf]);
                    mma16bf(c[mf][nf], ah[mf], bl[nf]);
                }
        }
        __syncthreads();
    }

#pragma unroll
    for (int mf = 0; mf < 4; mf++) {
#pragma unroll
        for (int nf = 0; nf < 4; nf++) {
            int col = colBlock + n0w + nf * 8 + 2 * tg;
            float2 bv = *(const float2*)(bias + col);
            int r0 = rowBlock + m0w + mf * 16 + g;
            float v0 = c[mf][nf][0] + bv.x;
            float v1 = c[mf][nf][1] + bv.y;
            float v2 = c[mf][nf][2] + bv.x;
            float v3 = c[mf][nf][3] + bv.y;
            if (mode == 1) {
                v0 = tf32f(v0); v1 = tf32f(v1); v2 = tf32f(v2); v3 = tf32f(v3);
            } else if (mode == 2) {
                v0 = tf32f(v0 * QSCALE); v1 = tf32f(v1 * QSCALE);
                v2 = tf32f(v2 * QSCALE); v3 = tf32f(v3 * QSCALE);
            }
            *(float2*)(C + (size_t)r0 * DM + col) = make_float2(v0, v1);
            *(float2*)(C + (size_t)(r0 + 8) * DM + col) = make_float2(v2, v3);
        }
    }
}

// ---------------------------------------------------------------------------
// Flash attention: tf32 mma, register softmax, 32 q-rows/warp,
// cp.async double-buffered K/V (values pre-rounded by GEMM epilogue),
// exp2-domain softmax (Q pre-scaled by 0.125*log2(e)).
// Block = 128 threads / 4 warps -> 128 query rows per block.
// ---------------------------------------------------------------------------
#define QKS 68
#define VST 72
#define KVBUF (64 * QKS + 64 * VST)   // floats per K/V buffer

__device__ __forceinline__ void attn_prefetch(
    uint32_t ks_a, uint32_t vs_a, const float* __restrict__ kbase,
    const float* __restrict__ vbase, int tid, int s0)
{
#pragma unroll
    for (int i = 0; i < 8; i++) {
        int c = tid + i * 128;
        int row = c >> 4, cc = c & 15;
        cp16(ks_a + (uint32_t)(row * QKS + cc * 4) * 4,
             kbase + (size_t)(s0 + row) * DM + cc * 4);
        cp16(vs_a + (uint32_t)(row * VST + cc * 4) * 4,
             vbase + (size_t)(s0 + row) * DM + cc * 4);
    }
}

__global__ __launch_bounds__(128) void attn_mma_kernel(
    const float* __restrict__ qg, const float* __restrict__ kg,
    const float* __restrict__ vg, float* __restrict__ ctx)
{
    extern __shared__ float smf[];
    float* qs = smf;                       // [128][QKS]
    const uint32_t sbase = smem_u32(smf);
    const uint32_t kv0 = sbase + 128 * QKS * 4;

    const int tid  = threadIdx.x;
    const int lane = tid & 31;
    const int warp = tid >> 5;
    const int g  = lane >> 2;
    const int tg = lane & 3;
    const int w32 = warp * 32;
    const int b = blockIdx.y >> 4;
    const int h = blockIdx.y & 15;
    const int q0 = blockIdx.x * 128;

    const float* kbase = kg + (size_t)(b * LSEQ) * DM + h * HD;
    const float* vbase = vg + (size_t)(b * LSEQ) * DM + h * HD;

    // kick off chunk 0 K/V prefetch first
    attn_prefetch(kv0, kv0 + 64 * QKS * 4, kbase, vbase, tid, 0);
    CP_COMMIT();

    // load Q (already scaled+rounded by GEMM epilogue)
    const float* qbase = qg + (size_t)(b * LSEQ + q0) * DM + h * HD;
    for (int p = tid; p < 128 * 16; p += 128) {
        int r  = p >> 4;
        int c4 = (p & 15) << 2;
        *(float4*)(qs + r * QKS + c4) =
            *(const float4*)(qbase + (size_t)r * DM + c4);
    }

    float m[4] = {-1e30f, -1e30f, -1e30f, -1e30f};
    float l[4] = {0.f, 0.f, 0.f, 0.f};
    float o0[8][4], o1[8][4];
#pragma unroll
    for (int nf = 0; nf < 8; nf++)
#pragma unroll
        for (int i = 0; i < 4; i++) { o0[nf][i] = 0.f; o1[nf][i] = 0.f; }

    const unsigned FULL = 0xffffffffu;
    const int srcA = (lane & ~3) | (tg >> 1);
    const int srcB = srcA + 2;

    for (int ci = 0; ci < 32; ci++) {
        if (ci < 31) {
            uint32_t nb = kv0 + ((ci + 1) & 1) * KVBUF * 4;
            attn_prefetch(nb, nb + 64 * QKS * 4, kbase, vbase, tid, (ci + 1) * 64);
            CP_COMMIT();
            CP_WAIT1();
        } else {
            CP_WAIT0();
        }
        __syncthreads();

        const float* ks = smf + 128 * QKS + (ci & 1) * KVBUF;
        const float* vs = ks + 64 * QKS;

        // --- scores for both row groups ---
        float sc0[8][4], sc1[8][4];
#pragma unroll
        for (int nf = 0; nf < 8; nf++)
#pragma unroll
            for (int i = 0; i < 4; i++) { sc0[nf][i] = 0.f; sc1[nf][i] = 0.f; }

#pragma unroll
        for (int k8 = 0; k8 < 64; k8 += 8) {
            unsigned a0[4], a1[4];
            const float* q00 = qs + (w32 + g) * QKS + k8 + tg;
            const float* q01 = qs + (w32 + g + 8) * QKS + k8 + tg;
            const float* q10 = qs + (w32 + 16 + g) * QKS + k8 + tg;
            const float* q11 = qs + (w32 + 24 + g) * QKS + k8 + tg;
            a0[0] = __float_as_uint(q00[0]);
            a0[1] = __float_as_uint(q01[0]);
            a0[2] = __float_as_uint(q00[4]);
            a0[3] = __float_as_uint(q01[4]);
            a1[0] = __float_as_uint(q10[0]);
            a1[1] = __float_as_uint(q11[0]);
            a1[2] = __float_as_uint(q10[4]);
            a1[3] = __float_as_uint(q11[4]);
#pragma unroll
            for (int nf = 0; nf < 8; nf++) {
                unsigned bb[2];
                const float* kr = ks + (nf * 8 + g) * QKS + k8 + tg;
                bb[0] = __float_as_uint(kr[0]);
                bb[1] = __float_as_uint(kr[4]);
                mma8(sc0[nf], a0, bb);
                mma8(sc1[nf], a1, bb);
            }
        }

        // --- register softmax in log2 domain ---
        float mx[4] = {-1e30f, -1e30f, -1e30f, -1e30f};
#pragma unroll
        for (int nf = 0; nf < 8; nf++) {
            mx[0] = fmaxf(mx[0], fmaxf(sc0[nf][0], sc0[nf][1]));
            mx[1] = fmaxf(mx[1], fmaxf(sc0[nf][2], sc0[nf][3]));
            mx[2] = fmaxf(mx[2], fmaxf(sc1[nf][0], sc1[nf][1]));
            mx[3] = fmaxf(mx[3], fmaxf(sc1[nf][2], sc1[nf][3]));
        }
        float al[4], mn[4], rs[4] = {0.f, 0.f, 0.f, 0.f};
#pragma unroll
        for (int r = 0; r < 4; r++) {
            mx[r] = fmaxf(mx[r], __shfl_xor_sync(FULL, mx[r], 1));
            mx[r] = fmaxf(mx[r], __shfl_xor_sync(FULL, mx[r], 2));
            mn[r] = fmaxf(m[r], mx[r]);
            al[r] = exp2f(m[r] - mn[r]);
        }
#pragma unroll
        for (int nf = 0; nf < 8; nf++) {
            float p0 = tf32f(exp2f(sc0[nf][0] - mn[0]));
            float p1 = tf32f(exp2f(sc0[nf][1] - mn[0]));
            float p2 = tf32f(exp2f(sc0[nf][2] - mn[1]));
            float p3 = tf32f(exp2f(sc0[nf][3] - mn[1]));
            sc0[nf][0] = p0; sc0[nf][1] = p1; sc0[nf][2] = p2; sc0[nf][3] = p3;
            rs[0] += p0 + p1; rs[1] += p2 + p3;
            p0 = tf32f(exp2f(sc1[nf][0] - mn[2]));
            p1 = tf32f(exp2f(sc1[nf][1] - mn[2]));
            p2 = tf32f(exp2f(sc1[nf][2] - mn[3]));
            p3 = tf32f(exp2f(sc1[nf][3] - mn[3]));
            sc1[nf][0] = p0; sc1[nf][1] = p1; sc1[nf][2] = p2; sc1[nf][3] = p3;
            rs[2] += p0 + p1; rs[3] += p2 + p3;
        }
#pragma unroll
        for (int r = 0; r < 4; r++) {
            rs[r] += __shfl_xor_sync(FULL, rs[r], 1);
            rs[r] += __shfl_xor_sync(FULL, rs[r], 2);
            l[r] = l[r] * al[r] + rs[r];
            m[r] = mn[r];
        }

#pragma unroll
        for (int nf = 0; nf < 8; nf++) {
            o0[nf][0] *= al[0]; o0[nf][1] *= al[0];
            o0[nf][2] *= al[1]; o0[nf][3] *= al[1];
            o1[nf][0] *= al[2]; o1[nf][1] *= al[2];
            o1[nf][2] *= al[3]; o1[nf][3] *= al[3];
        }

        // --- P·V: A-frags via quad shuffles, B-frags shared between groups ---
#pragma unroll
        for (int j = 0; j < 8; j++) {
            unsigned a0[4], a1[4];
            {
                float f00 = __shfl_sync(FULL, sc0[j][0], srcA);
                float f01 = __shfl_sync(FULL, sc0[j][1], srcA);
                float f10 = __shfl_sync(FULL, sc0[j][2], srcA);
                float f11 = __shfl_sync(FULL, sc0[j][3], srcA);
                float f20 = __shfl_sync(FULL, sc0[j][0], srcB);
                float f21 = __shfl_sync(FULL, sc0[j][1], srcB);
                float f30 = __shfl_sync(FULL, sc0[j][2], srcB);
                float f31 = __shfl_sync(FULL, sc0[j][3], srcB);
                a0[0] = __float_as_uint((tg & 1) ? f01 : f00);
                a0[1] = __float_as_uint((tg & 1) ? f11 : f10);
                a0[2] = __float_as_uint((tg & 1) ? f21 : f20);
                a0[3] = __float_as_uint((tg & 1) ? f31 : f30);
            }
            {
                float f00 = __shfl_sync(FULL, sc1[j][0], srcA);
                float f01 = __shfl_sync(FULL, sc1[j][1], srcA);
                float f10 = __shfl_sync(FULL, sc1[j][2], srcA);
                float f11 = __shfl_sync(FULL, sc1[j][3], srcA);
                float f20 = __shfl_sync(FULL, sc1[j][0], srcB);
                float f21 = __shfl_sync(FULL, sc1[j][1], srcB);
                float f30 = __shfl_sync(FULL, sc1[j][2], srcB);
                float f31 = __shfl_sync(FULL, sc1[j][3], srcB);
                a1[0] = __float_as_uint((tg & 1) ? f01 : f00);
                a1[1] = __float_as_uint((tg & 1) ? f11 : f10);
                a1[2] = __float_as_uint((tg & 1) ? f21 : f20);
                a1[3] = __float_as_uint((tg & 1) ? f31 : f30);
            }
#pragma unroll
            for (int nf = 0; nf < 8; nf++) {
                unsigned bb[2];
                const float* vr = vs + (j * 8 + tg) * VST + nf * 8 + g;
                bb[0] = __float_as_uint(vr[0]);
                bb[1] = __float_as_uint(vr[4 * VST]);
                mma8(o0[nf], a0, bb);
                mma8(o1[nf], a1, bb);
            }
        }
        __syncthreads();
    }

    float inv[4];
#pragma unroll
    for (int r = 0; r < 4; r++) inv[r] = 1.f / l[r];
    const int rowOff[4] = {0, 8, 16, 24};
    float* base = ctx + (size_t)(b * LSEQ + q0 + w32 + g) * DM + h * HD;
#pragma unroll
    for (int r = 0; r < 4; r++) {
        float* cb = base + (size_t)rowOff[r] * DM;
        float (*oo)[4] = (r < 2) ? o0 : o1;
        int i0 = (r & 1) ? 2 : 0;
#pragma unroll
        for (int nf = 0; nf < 8; nf++) {
            *(float2*)(cb + nf * 8 + 2 * tg) =
                make_float2(oo[nf][i0] * inv[r], oo[nf][i0 + 1] * inv[r]);
        }
    }
}

// ---------------------------------------------------------------------------
extern "C" void kernel_launch(void* const* d_in, const int* in_sizes, int n_in,
                              void* d_out, int out_size)
{
    const float* queries = (const float*)d_in[0];
    const float* keys    = (const float*)d_in[1];
    const float* values  = (const float*)d_in[2];
    const float* Wq      = (const float*)d_in[3];
    const float* bq      = (const float*)d_in[4];
    const float* Wk      = (const float*)d_in[5];
    const float* bk      = (const float*)d_in[6];
    const float* Wv      = (const float*)d_in[7];
    const float* bv      = (const float*)d_in[8];
    const float* Wo      = (const float*)d_in[9];
    const float* bo      = (const float*)d_in[10];
    float* out = (float*)d_out;

    float *qb, *kb, *vb, *cb;
    uint32_t *pah, *pal, *pwh, *pwl;
    cudaGetSymbolAddress((void**)&qb, g_q);
    cudaGetSymbolAddress((void**)&kb, g_k);
    cudaGetSymbolAddress((void**)&vb, g_v);
    cudaGetSymbolAddress((void**)&cb, g_ctx);
    cudaGetSymbolAddress((void**)&pah, g_pa_h);
    cudaGetSymbolAddress((void**)&pal, g_pa_l);
    cudaGetSymbolAddress((void**)&pwh, g_pw_h);
    cudaGetSymbolAddress((void**)&pwl, g_pw_l);

    const size_t gemm_sm = 2 * BUFSZ;                                  // 77824
    const size_t attn_sm = (size_t)(128 * QKS + 2 * KVBUF) * sizeof(float);

    cudaFuncSetAttribute(gemm_bf16x3_kernel,
                         cudaFuncAttributeMaxDynamicSharedMemorySize, (int)gemm_sm);
    cudaFuncSetAttribute(attn_mma_kernel,
                         cudaFuncAttributeMaxDynamicSharedMemorySize, (int)attn_sm);

    const int PA_BLOCKS = MROWS * DM / 4 / 256;   // 8192
    const int PW_BLOCKS = KHALF * DM / 4 / 256;   // 512
    dim3 ggrid(DM / 128, MROWS / 128);

    // Q projection (mode 2: scale+round for exp2-domain softmax)
    pack_a_kernel<<<PA_BLOCKS, 256>>>(queries, pah, pal);
    pack_w_kernel<<<PW_BLOCKS, 256>>>(Wq, pwh, pwl);
    gemm_bf16x3_kernel<<<ggrid, 256, gemm_sm>>>(pah, pal, pwh, pwl, bq, qb, 2);

    // K projection (mode 1: tf32 round)
    pack_a_kernel<<<PA_BLOCKS, 256>>>(keys, pah, pal);
    pack_w_kernel<<<PW_BLOCKS, 256>>>(Wk, pwh, pwl);
    gemm_bf16x3_kernel<<<ggrid, 256, gemm_sm>>>(pah, pal, pwh, pwl, bk, kb, 1);

    // V projection (mode 1)
    pack_a_kernel<<<PA_BLOCKS, 256>>>(values, pah, pal);
    pack_w_kernel<<<PW_BLOCKS, 256>>>(Wv, pwh, pwl);
    gemm_bf16x3_kernel<<<ggrid, 256, gemm_sm>>>(pah, pal, pwh, pwl, bv, vb, 1);

    // attention
    attn_mma_kernel<<<dim3(LSEQ / 128, BSZ * NH), 128, attn_sm>>>(qb, kb, vb, cb);

    // output projection (mode 0)
    pack_a_kernel<<<PA_BLOCKS, 256>>>(cb, pah, pal);
    pack_w_kernel<<<PW_BLOCKS, 256>>>(Wo, pwh, pwl);
    gemm_bf16x3_kernel<<<ggrid, 256, gemm_sm>>>(pah, pal, pwh, pwl, bo, out, 0);
}